// round 1
// baseline (speedup 1.0000x reference)
#include <cuda_runtime.h>
#include <cuda_bf16.h>
#include <math.h>

#define D_MODEL 1024
#define BSQ 4096              // B*S = 2*2048
#define D_FF  4096
#define NUM_HEADS 16
#define D_K 64

// ---------------- scratch (device globals; no allocation allowed) ----------------
__device__ float g_q   [(size_t)BSQ * D_MODEL];
__device__ float g_k   [(size_t)BSQ * D_MODEL];
__device__ float g_v   [(size_t)BSQ * D_MODEL];
__device__ float g_attn[(size_t)BSQ * D_MODEL];
__device__ float g_proj[(size_t)BSQ * D_MODEL];
__device__ float g_x1  [(size_t)BSQ * D_MODEL];
__device__ float g_ff  [(size_t)BSQ * D_FF];

// ---------------- GEMM: C[M,N] = A[M,K] * B[N,K]^T, optional exact GELU ----------
__device__ __forceinline__ float gelu_exact(float x) {
    return 0.5f * x * (1.0f + erff(x * 0.70710678118654752f));
}

template<bool GELU>
__global__ __launch_bounds__(256)
void gemm_nt_kernel(const float* __restrict__ A, const float* __restrict__ B,
                    float* __restrict__ C, int M, int N, int K)
{
    __shared__ float As[16][132];
    __shared__ float Bs[16][132];

    const int tid = threadIdx.x;
    const int tx = tid & 15;
    const int ty = tid >> 4;
    const int m0 = blockIdx.y * 128;
    const int n0 = blockIdx.x * 128;

    float acc[8][8];
#pragma unroll
    for (int i = 0; i < 8; i++)
#pragma unroll
        for (int j = 0; j < 8; j++) acc[i][j] = 0.f;

    for (int k0 = 0; k0 < K; k0 += 16) {
        // load tiles (512 float4 each), transpose into As[k][m], Bs[k][n]
#pragma unroll
        for (int q = 0; q < 2; q++) {
            int f   = q * 256 + tid;     // 0..511
            int row = f >> 2;            // 0..127
            int kc  = (f & 3) * 4;       // 0,4,8,12
            float4 a = *(const float4*)&A[(size_t)(m0 + row) * K + k0 + kc];
            As[kc + 0][row] = a.x; As[kc + 1][row] = a.y;
            As[kc + 2][row] = a.z; As[kc + 3][row] = a.w;
            float4 b = *(const float4*)&B[(size_t)(n0 + row) * K + k0 + kc];
            Bs[kc + 0][row] = b.x; Bs[kc + 1][row] = b.y;
            Bs[kc + 2][row] = b.z; Bs[kc + 3][row] = b.w;
        }
        __syncthreads();

#pragma unroll
        for (int kk = 0; kk < 16; kk++) {
            float4 a0 = *(const float4*)&As[kk][ty * 4];
            float4 a1 = *(const float4*)&As[kk][64 + ty * 4];
            float4 b0 = *(const float4*)&Bs[kk][tx * 4];
            float4 b1 = *(const float4*)&Bs[kk][64 + tx * 4];
            float a[8] = {a0.x, a0.y, a0.z, a0.w, a1.x, a1.y, a1.z, a1.w};
            float b[8] = {b0.x, b0.y, b0.z, b0.w, b1.x, b1.y, b1.z, b1.w};
#pragma unroll
            for (int i = 0; i < 8; i++)
#pragma unroll
                for (int j = 0; j < 8; j++)
                    acc[i][j] = fmaf(a[i], b[j], acc[i][j]);
        }
        __syncthreads();
    }

#pragma unroll
    for (int ih = 0; ih < 2; ih++)
#pragma unroll
        for (int i = 0; i < 4; i++) {
            int r = m0 + ih * 64 + ty * 4 + i;
#pragma unroll
            for (int jh = 0; jh < 2; jh++) {
                float4 v;
                v.x = acc[ih * 4 + i][jh * 4 + 0];
                v.y = acc[ih * 4 + i][jh * 4 + 1];
                v.z = acc[ih * 4 + i][jh * 4 + 2];
                v.w = acc[ih * 4 + i][jh * 4 + 3];
                if (GELU) {
                    v.x = gelu_exact(v.x); v.y = gelu_exact(v.y);
                    v.z = gelu_exact(v.z); v.w = gelu_exact(v.w);
                }
                *(float4*)&C[(size_t)r * N + n0 + jh * 64 + tx * 4] = v;
            }
        }
}

// ---------------- Flash attention: per (b,h), 64 query rows per block -----------
// Q/K/V are [BSQ, 1024] with head h occupying cols h*64..h*64+63.
__global__ __launch_bounds__(256)
void attn_kernel(const float* __restrict__ Q, const float* __restrict__ K,
                 const float* __restrict__ V, float* __restrict__ O)
{
    __shared__ float Qs[64 * 64];   // [m][d] plain
    __shared__ float Ks[64 * 64];   // K: [c][d] xor-swizzled by (c>>2); later reused for V [k][d] plain
    __shared__ float Ps[64 * 64];   // [m][n] plain

    const int tid = threadIdx.x;
    const int tx = tid & 15;
    const int ty = tid >> 4;
    const int bh = blockIdx.y;
    const int b  = bh >> 4;
    const int h  = bh & 15;
    const int m0 = blockIdx.x * 64;
    const size_t rowbase = (size_t)b * 2048;
    const int coff = h * 64;

    // load Q (pre-scaled by 1/sqrt(64) = 0.125)
#pragma unroll
    for (int q = 0; q < 4; q++) {
        int f = q * 256 + tid;     // float4 index, 0..1023
        int r = f >> 4;            // 0..63
        int g = f & 15;            // float4-group within row
        float4 val = *(const float4*)&Q[(rowbase + m0 + r) * D_MODEL + coff + g * 4];
        val.x *= 0.125f; val.y *= 0.125f; val.z *= 0.125f; val.w *= 0.125f;
        *(float4*)&Qs[r * 64 + g * 4] = val;
    }

    float m_r[4], l_r[4], acc[4][4];
#pragma unroll
    for (int i = 0; i < 4; i++) {
        m_r[i] = -1e30f; l_r[i] = 0.f;
#pragma unroll
        for (int j = 0; j < 4; j++) acc[i][j] = 0.f;
    }

    for (int kb = 0; kb < 32; kb++) {
        const int n0 = kb * 64;
        // load K tile, xor-swizzled groups
#pragma unroll
        for (int q = 0; q < 4; q++) {
            int f = q * 256 + tid;
            int c = f >> 4;
            int g = f & 15;
            float4 val = *(const float4*)&K[(rowbase + n0 + c) * D_MODEL + coff + g * 4];
            int gp = g ^ ((c >> 2) & 15);
            *(float4*)&Ks[c * 64 + gp * 4] = val;
        }
        __syncthreads();

        // S tile = Q * K^T (scaled already)
        float s[4][4];
#pragma unroll
        for (int i = 0; i < 4; i++)
#pragma unroll
            for (int j = 0; j < 4; j++) s[i][j] = 0.f;

#pragma unroll
        for (int g = 0; g < 16; g++) {
            float4 qv[4], kv[4];
#pragma unroll
            for (int i = 0; i < 4; i++)
                qv[i] = *(const float4*)&Qs[(ty * 4 + i) * 64 + g * 4];
#pragma unroll
            for (int j = 0; j < 4; j++) {
                int c = tx * 4 + j;
                kv[j] = *(const float4*)&Ks[c * 64 + ((g ^ (c >> 2)) & 15) * 4];
            }
#pragma unroll
            for (int i = 0; i < 4; i++)
#pragma unroll
                for (int j = 0; j < 4; j++)
                    s[i][j] = fmaf(qv[i].x, kv[j].x,
                              fmaf(qv[i].y, kv[j].y,
                              fmaf(qv[i].z, kv[j].z,
                              fmaf(qv[i].w, kv[j].w, s[i][j]))));
        }

        // online softmax (rows of 64 spread across 16 tx lanes)
#pragma unroll
        for (int i = 0; i < 4; i++) {
            float mx = fmaxf(fmaxf(s[i][0], s[i][1]), fmaxf(s[i][2], s[i][3]));
#pragma unroll
            for (int off = 8; off; off >>= 1)
                mx = fmaxf(mx, __shfl_xor_sync(0xffffffffu, mx, off));
            float mnew = fmaxf(m_r[i], mx);
            float p0 = __expf(s[i][0] - mnew);
            float p1 = __expf(s[i][1] - mnew);
            float p2 = __expf(s[i][2] - mnew);
            float p3 = __expf(s[i][3] - mnew);
            float sum = p0 + p1 + p2 + p3;
#pragma unroll
            for (int off = 8; off; off >>= 1)
                sum += __shfl_xor_sync(0xffffffffu, sum, off);
            float sc = __expf(m_r[i] - mnew);
            l_r[i] = l_r[i] * sc + sum;
            m_r[i] = mnew;
#pragma unroll
            for (int j = 0; j < 4; j++) acc[i][j] *= sc;
            float4 pv = make_float4(p0, p1, p2, p3);
            *(float4*)&Ps[(ty * 4 + i) * 64 + tx * 4] = pv;
        }
        __syncthreads();   // everyone done reading Ks(K) and writing Ps

        // load V tile into Ks buffer (plain layout)
#pragma unroll
        for (int q = 0; q < 4; q++) {
            int f = q * 256 + tid;
            int r = f >> 4;
            int g = f & 15;
            *(float4*)&Ks[r * 64 + g * 4] =
                *(const float4*)&V[(rowbase + n0 + r) * D_MODEL + coff + g * 4];
        }
        __syncthreads();

        // acc += P @ V
#pragma unroll
        for (int k4 = 0; k4 < 16; k4++) {
            float4 p4[4], vv[4];
#pragma unroll
            for (int i = 0; i < 4; i++)
                p4[i] = *(const float4*)&Ps[(ty * 4 + i) * 64 + k4 * 4];
#pragma unroll
            for (int kk = 0; kk < 4; kk++)
                vv[kk] = *(const float4*)&Ks[(k4 * 4 + kk) * 64 + tx * 4];
#pragma unroll
            for (int i = 0; i < 4; i++) {
                float pa[4] = {p4[i].x, p4[i].y, p4[i].z, p4[i].w};
#pragma unroll
                for (int kk = 0; kk < 4; kk++) {
                    acc[i][0] = fmaf(pa[kk], vv[kk].x, acc[i][0]);
                    acc[i][1] = fmaf(pa[kk], vv[kk].y, acc[i][1]);
                    acc[i][2] = fmaf(pa[kk], vv[kk].z, acc[i][2]);
                    acc[i][3] = fmaf(pa[kk], vv[kk].w, acc[i][3]);
                }
            }
        }
        __syncthreads();   // before next iter overwrites Ks/Ps
    }

    // write O (already back in [B,S,H*Dk] layout)
#pragma unroll
    for (int i = 0; i < 4; i++) {
        float inv = 1.0f / l_r[i];
        float4 o = make_float4(acc[i][0] * inv, acc[i][1] * inv,
                               acc[i][2] * inv, acc[i][3] * inv);
        *(float4*)&O[(rowbase + m0 + ty * 4 + i) * D_MODEL + coff + tx * 4] = o;
    }
}

// ---------------- fused residual add + LayerNorm -------------------------------
__global__ __launch_bounds__(256)
void add_ln_kernel(const float* __restrict__ X, const float* __restrict__ Y,
                   const float* __restrict__ G, const float* __restrict__ Bv,
                   float* __restrict__ Out)
{
    const int row = blockIdx.x;
    const int t = threadIdx.x;
    const size_t base = (size_t)row * D_MODEL + t * 4;

    float4 a = *(const float4*)&X[base];
    float4 c = *(const float4*)&Y[base];
    float v0 = a.x + c.x, v1 = a.y + c.y, v2 = a.z + c.z, v3 = a.w + c.w;

    float s  = v0 + v1 + v2 + v3;
    float sq = v0 * v0 + v1 * v1 + v2 * v2 + v3 * v3;
#pragma unroll
    for (int off = 16; off; off >>= 1) {
        s  += __shfl_xor_sync(0xffffffffu, s,  off);
        sq += __shfl_xor_sync(0xffffffffu, sq, off);
    }

    __shared__ float sh_s[8], sh_q[8];
    __shared__ float sh_stats[2];
    const int w = t >> 5, lane = t & 31;
    if (lane == 0) { sh_s[w] = s; sh_q[w] = sq; }
    __syncthreads();
    if (t < 32) {
        float ts = (lane < 8) ? sh_s[lane] : 0.f;
        float tq = (lane < 8) ? sh_q[lane] : 0.f;
#pragma unroll
        for (int off = 4; off; off >>= 1) {
            ts += __shfl_xor_sync(0xffffffffu, ts, off);
            tq += __shfl_xor_sync(0xffffffffu, tq, off);
        }
        if (lane == 0) {
            float mean = ts * (1.0f / D_MODEL);
            float var  = tq * (1.0f / D_MODEL) - mean * mean;
            sh_stats[0] = mean;
            sh_stats[1] = rsqrtf(var + 1e-5f);
        }
    }
    __syncthreads();
    const float mean = sh_stats[0];
    const float rstd = sh_stats[1];

    float4 gg = *(const float4*)&G[t * 4];
    float4 bb = *(const float4*)&Bv[t * 4];
    float4 o;
    o.x = (v0 - mean) * rstd * gg.x + bb.x;
    o.y = (v1 - mean) * rstd * gg.y + bb.y;
    o.z = (v2 - mean) * rstd * gg.z + bb.z;
    o.w = (v3 - mean) * rstd * gg.w + bb.w;
    *(float4*)&Out[base] = o;
}

// ---------------- launch --------------------------------------------------------
extern "C" void kernel_launch(void* const* d_in, const int* in_sizes, int n_in,
                              void* d_out, int out_size)
{
    const float* x  = (const float*)d_in[0];
    const float* Wq = (const float*)d_in[1];
    const float* Wk = (const float*)d_in[2];
    const float* Wv = (const float*)d_in[3];
    const float* Wo = (const float*)d_in[4];
    const float* W1 = (const float*)d_in[5];
    const float* W2 = (const float*)d_in[6];
    const float* g1 = (const float*)d_in[7];
    const float* b1 = (const float*)d_in[8];
    const float* g2 = (const float*)d_in[9];
    const float* b2 = (const float*)d_in[10];

    float *q, *k, *v, *attn, *proj, *x1, *ff;
    cudaGetSymbolAddress((void**)&q,    g_q);
    cudaGetSymbolAddress((void**)&k,    g_k);
    cudaGetSymbolAddress((void**)&v,    g_v);
    cudaGetSymbolAddress((void**)&attn, g_attn);
    cudaGetSymbolAddress((void**)&proj, g_proj);
    cudaGetSymbolAddress((void**)&x1,   g_x1);
    cudaGetSymbolAddress((void**)&ff,   g_ff);

    dim3 blk(256);
    dim3 grid_1024(D_MODEL / 128, BSQ / 128);   // (8, 32)
    dim3 grid_ff1 (D_FF  / 128, BSQ / 128);     // (32, 32)

    // QKV projections
    gemm_nt_kernel<false><<<grid_1024, blk>>>(x, Wq, q, BSQ, D_MODEL, D_MODEL);
    gemm_nt_kernel<false><<<grid_1024, blk>>>(x, Wk, k, BSQ, D_MODEL, D_MODEL);
    gemm_nt_kernel<false><<<grid_1024, blk>>>(x, Wv, v, BSQ, D_MODEL, D_MODEL);

    // attention
    attn_kernel<<<dim3(32, 32), blk>>>(q, k, v, attn);

    // output projection
    gemm_nt_kernel<false><<<grid_1024, blk>>>(attn, Wo, proj, BSQ, D_MODEL, D_MODEL);

    // residual + LN1
    add_ln_kernel<<<BSQ, blk>>>(x, proj, g1, b1, x1);

    // FF1 (+GELU) and FF2
    gemm_nt_kernel<true ><<<grid_ff1,  blk>>>(x1, W1, ff, BSQ, D_FF, D_MODEL);
    gemm_nt_kernel<false><<<grid_1024, blk>>>(ff, W2, proj, BSQ, D_MODEL, D_FF);

    // residual + LN2 -> output
    add_ln_kernel<<<BSQ, blk>>>(x1, proj, g2, b2, (float*)d_out);
}

// round 3
// speedup vs baseline: 1.8623x; 1.8623x over previous
#include <cuda_runtime.h>
#include <cuda_bf16.h>
#include <math.h>
#include <stdint.h>

#define D_MODEL 1024
#define BSQ 4096              // B*S = 2*2048
#define D_FF  4096

// ---------------- scratch (device globals; no allocation allowed) ----------------
__device__ float g_qkv [(size_t)BSQ * 3072];     // fused QKV output
__device__ float g_attn[(size_t)BSQ * D_MODEL];
__device__ float g_proj[(size_t)BSQ * D_MODEL];
__device__ float g_x1  [(size_t)BSQ * D_MODEL];
__device__ __nv_bfloat16 g_ahi[(size_t)BSQ * D_MODEL];
__device__ __nv_bfloat16 g_alo[(size_t)BSQ * D_MODEL];
__device__ __nv_bfloat16 g_fhi[(size_t)BSQ * D_FF];
__device__ __nv_bfloat16 g_flo[(size_t)BSQ * D_FF];
#define W_ELEMS 12582912   // 3M (QKV) + 1M (Wo) + 4M (W1) + 4M (W2)
__device__ __nv_bfloat16 g_whi[W_ELEMS];
__device__ __nv_bfloat16 g_wlo[W_ELEMS];
#define OFF_WQ 0
#define OFF_WK 1048576
#define OFF_WV 2097152
#define OFF_WO 3145728
#define OFF_W1 4194304
#define OFF_W2 8388608

// ---------------- helpers --------------------------------------------------------
__device__ __forceinline__ uint32_t smem_to_u32(const void* p) {
    uint32_t a;
    asm("{ .reg .u64 t; cvta.to.shared.u64 t, %1; cvt.u32.u64 %0, t; }" : "=r"(a) : "l"(p));
    return a;
}
#define SWZ(off) ((off) ^ (((off) >> 3) & 0x70))

__device__ __forceinline__ void cp_async16(uint32_t dst, const void* src) {
    asm volatile("cp.async.cg.shared.global [%0], [%1], 16;" :: "r"(dst), "l"(src) : "memory");
}
__device__ __forceinline__ void cp_commit() {
    asm volatile("cp.async.commit_group;" ::: "memory");
}
template<int N>
__device__ __forceinline__ void cp_wait() {
    asm volatile("cp.async.wait_group %0;" :: "n"(N) : "memory");
}
__device__ __forceinline__ void ldsm4(uint32_t* r, uint32_t addr) {
    asm volatile("ldmatrix.sync.aligned.m8n8.x4.shared.b16 {%0,%1,%2,%3}, [%4];"
                 : "=r"(r[0]), "=r"(r[1]), "=r"(r[2]), "=r"(r[3]) : "r"(addr));
}
__device__ __forceinline__ void mma16816(float* d, const uint32_t* a, const uint32_t* b) {
    asm volatile("mma.sync.aligned.m16n8k16.row.col.f32.bf16.bf16.f32 "
                 "{%0,%1,%2,%3}, {%4,%5,%6,%7}, {%8,%9}, {%0,%1,%2,%3};"
                 : "+f"(d[0]), "+f"(d[1]), "+f"(d[2]), "+f"(d[3])
                 : "r"(a[0]), "r"(a[1]), "r"(a[2]), "r"(a[3]), "r"(b[0]), "r"(b[1]));
}
__device__ __forceinline__ float gelu_exact(float x) {
    return 0.5f * x * (1.0f + erff(x * 0.70710678118654752f));
}

// ---------------- fp32 -> (hi, lo) bf16 split conversion -------------------------
__global__ __launch_bounds__(256)
void convert_hl(const float* __restrict__ src, __nv_bfloat16* __restrict__ hi,
                __nv_bfloat16* __restrict__ lo, int n4)
{
    int i = blockIdx.x * blockDim.x + threadIdx.x;
    if (i >= n4) return;
    float4 v = ((const float4*)src)[i];
    __nv_bfloat16 h0 = __float2bfloat16(v.x), h1 = __float2bfloat16(v.y);
    __nv_bfloat16 h2 = __float2bfloat16(v.z), h3 = __float2bfloat16(v.w);
    __nv_bfloat16 l0 = __float2bfloat16(v.x - __bfloat162float(h0));
    __nv_bfloat16 l1 = __float2bfloat16(v.y - __bfloat162float(h1));
    __nv_bfloat16 l2 = __float2bfloat16(v.z - __bfloat162float(h2));
    __nv_bfloat16 l3 = __float2bfloat16(v.w - __bfloat162float(h3));
    ((__nv_bfloat162*)hi)[2 * i + 0] = __nv_bfloat162(h0, h1);
    ((__nv_bfloat162*)hi)[2 * i + 1] = __nv_bfloat162(h2, h3);
    ((__nv_bfloat162*)lo)[2 * i + 0] = __nv_bfloat162(l0, l1);
    ((__nv_bfloat162*)lo)[2 * i + 1] = __nv_bfloat162(l2, l3);
}

// ---------------- mma.sync GEMM: C[M,N] = A[M,K]*B[N,K]^T (bf16x3 split) ---------
// Tile 128x128, K_TILE=64, 2-stage cp.async pipeline, 8 warps of 64x32 each.
#define STAGE_BYTES 65536   // 4 tiles x 16KB (Ahi, Alo, Bhi, Blo), swizzled
#define SMEM_BYTES  (2 * STAGE_BYTES)

template<bool GELU, bool BF16OUT>
__global__ __launch_bounds__(256)
void mma_gemm(const __nv_bfloat16* __restrict__ Ah, const __nv_bfloat16* __restrict__ Al,
              const __nv_bfloat16* __restrict__ Bh, const __nv_bfloat16* __restrict__ Bl,
              float* __restrict__ C, __nv_bfloat16* __restrict__ Ch,
              __nv_bfloat16* __restrict__ Cl, int M, int N, int K)
{
    extern __shared__ __align__(1024) char smem[];
    const uint32_t sb = smem_to_u32(smem);
    const int tid  = threadIdx.x;
    const int wid  = tid >> 5;
    const int lane = tid & 31;
    const int m0 = blockIdx.y * 128;
    const int n0 = blockIdx.x * 128;
    const int mw = (wid >> 2) * 64;   // warp m offset within tile
    const int nw = (wid & 3) * 32;    // warp n offset within tile

    float acc[4][4][4];
#pragma unroll
    for (int i = 0; i < 4; i++)
#pragma unroll
        for (int j = 0; j < 4; j++)
#pragma unroll
            for (int e = 0; e < 4; e++) acc[i][j][e] = 0.f;

    // per-thread load geometry: idx i in 0..15 -> mat (0..3), row r, 16B group g
    const int rsub = tid >> 3;       // 0..31
    const int g    = tid & 7;        // 0..7

    auto load_stage = [&](int t) {
        const int k0 = t << 6;
        const uint32_t stage = sb + (t & 1) * STAGE_BYTES;
#pragma unroll
        for (int i = 0; i < 16; i++) {
            const int mat = i >> 2;
            const int r = (i & 3) * 32 + rsub;
            const __nv_bfloat16* src = (mat == 0) ? Ah : (mat == 1) ? Al
                                      : (mat == 2) ? Bh : Bl;
            const int row0 = (mat < 2) ? m0 : n0;
            cp_async16(stage + mat * 16384 + SWZ(r * 128 + g * 16),
                       &src[(size_t)(row0 + r) * K + k0 + g * 8]);
        }
        cp_commit();
    };

    const int nT = K >> 6;
    load_stage(0);

    for (int t = 0; t < nT; t++) {
        if (t + 1 < nT) { load_stage(t + 1); cp_wait<1>(); }
        else            { cp_wait<0>(); }
        __syncthreads();

        const uint32_t stage = sb + (t & 1) * STAGE_BYTES;
#pragma unroll
        for (int kk = 0; kk < 4; kk++) {
            const int kbyte = kk * 32;
            uint32_t ah[4][4], al[4][4], bh[2][4], bl[2][4];
            // A fragments: row = mw + mt*16 + lane%16 ; col = kbyte + (lane/16)*16
#pragma unroll
            for (int mt = 0; mt < 4; mt++) {
                const int off = (mw + mt * 16 + (lane & 15)) * 128 + kbyte + (lane >> 4) * 16;
                ldsm4(ah[mt], stage + 0     + SWZ(off));
                ldsm4(al[mt], stage + 16384 + SWZ(off));
            }
            // B fragments: row = nw + p*16 + (lane>>4)*8 + lane%8 ; col = kbyte + ((lane>>3)&1)*16
#pragma unroll
            for (int p = 0; p < 2; p++) {
                const int off = (nw + p * 16 + (lane >> 4) * 8 + (lane & 7)) * 128
                              + kbyte + ((lane >> 3) & 1) * 16;
                ldsm4(bh[p], stage + 32768 + SWZ(off));
                ldsm4(bl[p], stage + 49152 + SWZ(off));
            }
#pragma unroll
            for (int mt = 0; mt < 4; mt++)
#pragma unroll
                for (int nt = 0; nt < 4; nt++) {
                    const uint32_t* bhf = &bh[nt >> 1][(nt & 1) * 2];
                    const uint32_t* blf = &bl[nt >> 1][(nt & 1) * 2];
                    mma16816(acc[mt][nt], ah[mt], bhf);   // Ah*Bh
                    mma16816(acc[mt][nt], ah[mt], blf);   // Ah*Bl
                    mma16816(acc[mt][nt], al[mt], bhf);   // Al*Bh
                }
        }
        __syncthreads();
    }

    // epilogue: d fragment -> lane: rows l/4 and l/4+8, cols 2*(l%4)..+1
    const int er0 = m0 + mw + (lane >> 2);
    const int ec  = n0 + nw + 2 * (lane & 3);
#pragma unroll
    for (int mt = 0; mt < 4; mt++)
#pragma unroll
        for (int nt = 0; nt < 4; nt++) {
#pragma unroll
            for (int half = 0; half < 2; half++) {
                const int row = er0 + mt * 16 + half * 8;
                const int col = ec + nt * 8;
                float v0 = acc[mt][nt][half * 2 + 0];
                float v1 = acc[mt][nt][half * 2 + 1];
                if (GELU) { v0 = gelu_exact(v0); v1 = gelu_exact(v1); }
                if (BF16OUT) {
                    __nv_bfloat16 h0 = __float2bfloat16(v0);
                    __nv_bfloat16 h1 = __float2bfloat16(v1);
                    __nv_bfloat16 l0 = __float2bfloat16(v0 - __bfloat162float(h0));
                    __nv_bfloat16 l1 = __float2bfloat16(v1 - __bfloat162float(h1));
                    *(__nv_bfloat162*)&Ch[(size_t)row * N + col] = __nv_bfloat162(h0, h1);
                    *(__nv_bfloat162*)&Cl[(size_t)row * N + col] = __nv_bfloat162(l0, l1);
                } else {
                    *(float2*)&C[(size_t)row * N + col] = make_float2(v0, v1);
                }
            }
        }
}

// ---------------- Flash attention (FFMA; strided QKV input) ----------------------
__global__ __launch_bounds__(256)
void attn_kernel(const float* __restrict__ Q, const float* __restrict__ K,
                 const float* __restrict__ V, float* __restrict__ O, int ld)
{
    __shared__ float Qs[64 * 64];
    __shared__ float Ks[64 * 64];
    __shared__ float Ps[64 * 64];

    const int tid = threadIdx.x;
    const int tx = tid & 15;
    const int ty = tid >> 4;
    const int bh = blockIdx.y;
    const int b  = bh >> 4;
    const int h  = bh & 15;
    const int m0 = blockIdx.x * 64;
    const size_t rowbase = (size_t)b * 2048;
    const int coff = h * 64;

#pragma unroll
    for (int q = 0; q < 4; q++) {
        int f = q * 256 + tid;
        int r = f >> 4;
        int gg = f & 15;
        float4 val = *(const float4*)&Q[(rowbase + m0 + r) * ld + coff + gg * 4];
        val.x *= 0.125f; val.y *= 0.125f; val.z *= 0.125f; val.w *= 0.125f;
        *(float4*)&Qs[r * 64 + gg * 4] = val;
    }

    float m_r[4], l_r[4], acc[4][4];
#pragma unroll
    for (int i = 0; i < 4; i++) {
        m_r[i] = -1e30f; l_r[i] = 0.f;
#pragma unroll
        for (int j = 0; j < 4; j++) acc[i][j] = 0.f;
    }

    for (int kb = 0; kb < 32; kb++) {
        const int n0 = kb * 64;
#pragma unroll
        for (int q = 0; q < 4; q++) {
            int f = q * 256 + tid;
            int c = f >> 4;
            int gg = f & 15;
            float4 val = *(const float4*)&K[(rowbase + n0 + c) * ld + coff + gg * 4];
            int gp = gg ^ ((c >> 2) & 15);
            *(float4*)&Ks[c * 64 + gp * 4] = val;
        }
        __syncthreads();

        float s[4][4];
#pragma unroll
        for (int i = 0; i < 4; i++)
#pragma unroll
            for (int j = 0; j < 4; j++) s[i][j] = 0.f;

#pragma unroll
        for (int gg = 0; gg < 16; gg++) {
            float4 qv[4], kv[4];
#pragma unroll
            for (int i = 0; i < 4; i++)
                qv[i] = *(const float4*)&Qs[(ty * 4 + i) * 64 + gg * 4];
#pragma unroll
            for (int j = 0; j < 4; j++) {
                int c = tx * 4 + j;
                kv[j] = *(const float4*)&Ks[c * 64 + ((gg ^ (c >> 2)) & 15) * 4];
            }
#pragma unroll
            for (int i = 0; i < 4; i++)
#pragma unroll
                for (int j = 0; j < 4; j++)
                    s[i][j] = fmaf(qv[i].x, kv[j].x,
                              fmaf(qv[i].y, kv[j].y,
                              fmaf(qv[i].z, kv[j].z,
                              fmaf(qv[i].w, kv[j].w, s[i][j]))));
        }

#pragma unroll
        for (int i = 0; i < 4; i++) {
            float mx = fmaxf(fmaxf(s[i][0], s[i][1]), fmaxf(s[i][2], s[i][3]));
#pragma unroll
            for (int off = 8; off; off >>= 1)
                mx = fmaxf(mx, __shfl_xor_sync(0xffffffffu, mx, off));
            float mnew = fmaxf(m_r[i], mx);
            float p0 = __expf(s[i][0] - mnew);
            float p1 = __expf(s[i][1] - mnew);
            float p2 = __expf(s[i][2] - mnew);
            float p3 = __expf(s[i][3] - mnew);
            float sum = p0 + p1 + p2 + p3;
#pragma unroll
            for (int off = 8; off; off >>= 1)
                sum += __shfl_xor_sync(0xffffffffu, sum, off);
            float sc = __expf(m_r[i] - mnew);
            l_r[i] = l_r[i] * sc + sum;
            m_r[i] = mnew;
#pragma unroll
            for (int j = 0; j < 4; j++) acc[i][j] *= sc;
            float4 pv = make_float4(p0, p1, p2, p3);
            *(float4*)&Ps[(ty * 4 + i) * 64 + tx * 4] = pv;
        }
        __syncthreads();

#pragma unroll
        for (int q = 0; q < 4; q++) {
            int f = q * 256 + tid;
            int r = f >> 4;
            int gg = f & 15;
            *(float4*)&Ks[r * 64 + gg * 4] =
                *(const float4*)&V[(rowbase + n0 + r) * ld + coff + gg * 4];
        }
        __syncthreads();

#pragma unroll
        for (int k4 = 0; k4 < 16; k4++) {
            float4 p4[4], vv[4];
#pragma unroll
            for (int i = 0; i < 4; i++)
                p4[i] = *(const float4*)&Ps[(ty * 4 + i) * 64 + k4 * 4];
#pragma unroll
            for (int kk = 0; kk < 4; kk++)
                vv[kk] = *(const float4*)&Ks[(k4 * 4 + kk) * 64 + tx * 4];
#pragma unroll
            for (int i = 0; i < 4; i++) {
                float pa[4] = {p4[i].x, p4[i].y, p4[i].z, p4[i].w};
#pragma unroll
                for (int kk = 0; kk < 4; kk++) {
                    acc[i][0] = fmaf(pa[kk], vv[kk].x, acc[i][0]);
                    acc[i][1] = fmaf(pa[kk], vv[kk].y, acc[i][1]);
                    acc[i][2] = fmaf(pa[kk], vv[kk].z, acc[i][2]);
                    acc[i][3] = fmaf(pa[kk], vv[kk].w, acc[i][3]);
                }
            }
        }
        __syncthreads();
    }

#pragma unroll
    for (int i = 0; i < 4; i++) {
        float inv = 1.0f / l_r[i];
        float4 o = make_float4(acc[i][0] * inv, acc[i][1] * inv,
                               acc[i][2] * inv, acc[i][3] * inv);
        *(float4*)&O[(rowbase + m0 + ty * 4 + i) * D_MODEL + coff + tx * 4] = o;
    }
}

// ---------------- fused residual add + LayerNorm (+ optional hi/lo split out) ----
__global__ __launch_bounds__(256)
void add_ln_kernel(const float* __restrict__ X, const float* __restrict__ Y,
                   const float* __restrict__ G, const float* __restrict__ Bv,
                   float* __restrict__ Out, __nv_bfloat16* __restrict__ Hn,
                   __nv_bfloat16* __restrict__ Ln)
{
    const int row = blockIdx.x;
    const int t = threadIdx.x;
    const size_t base = (size_t)row * D_MODEL + t * 4;

    float4 a = *(const float4*)&X[base];
    float4 c = *(const float4*)&Y[base];
    float v0 = a.x + c.x, v1 = a.y + c.y, v2 = a.z + c.z, v3 = a.w + c.w;

    float s  = v0 + v1 + v2 + v3;
    float sq = v0 * v0 + v1 * v1 + v2 * v2 + v3 * v3;
#pragma unroll
    for (int off = 16; off; off >>= 1) {
        s  += __shfl_xor_sync(0xffffffffu, s,  off);
        sq += __shfl_xor_sync(0xffffffffu, sq, off);
    }

    __shared__ float sh_s[8], sh_q[8];
    __shared__ float sh_stats[2];
    const int w = t >> 5, lane = t & 31;
    if (lane == 0) { sh_s[w] = s; sh_q[w] = sq; }
    __syncthreads();
    if (t < 32) {
        float ts = (lane < 8) ? sh_s[lane] : 0.f;
        float tq = (lane < 8) ? sh_q[lane] : 0.f;
#pragma unroll
        for (int off = 4; off; off >>= 1) {
            ts += __shfl_xor_sync(0xffffffffu, ts, off);
            tq += __shfl_xor_sync(0xffffffffu, tq, off);
        }
        if (lane == 0) {
            float mean = ts * (1.0f / D_MODEL);
            float var  = tq * (1.0f / D_MODEL) - mean * mean;
            sh_stats[0] = mean;
            sh_stats[1] = rsqrtf(var + 1e-5f);
        }
    }
    __syncthreads();
    const float mean = sh_stats[0];
    const float rstd = sh_stats[1];

    float4 gg = *(const float4*)&G[t * 4];
    float4 bb = *(const float4*)&Bv[t * 4];
    float4 o;
    o.x = (v0 - mean) * rstd * gg.x + bb.x;
    o.y = (v1 - mean) * rstd * gg.y + bb.y;
    o.z = (v2 - mean) * rstd * gg.z + bb.z;
    o.w = (v3 - mean) * rstd * gg.w + bb.w;
    *(float4*)&Out[base] = o;

    if (Hn) {
        __nv_bfloat16 h0 = __float2bfloat16(o.x), h1 = __float2bfloat16(o.y);
        __nv_bfloat16 h2 = __float2bfloat16(o.z), h3 = __float2bfloat16(o.w);
        __nv_bfloat16 l0 = __float2bfloat16(o.x - __bfloat162float(h0));
        __nv_bfloat16 l1 = __float2bfloat16(o.y - __bfloat162float(h1));
        __nv_bfloat16 l2 = __float2bfloat16(o.z - __bfloat162float(h2));
        __nv_bfloat16 l3 = __float2bfloat16(o.w - __bfloat162float(h3));
        *(__nv_bfloat162*)&Hn[base]     = __nv_bfloat162(h0, h1);
        *(__nv_bfloat162*)&Hn[base + 2] = __nv_bfloat162(h2, h3);
        *(__nv_bfloat162*)&Ln[base]     = __nv_bfloat162(l0, l1);
        *(__nv_bfloat162*)&Ln[base + 2] = __nv_bfloat162(l2, l3);
    }
}

// ---------------- launch --------------------------------------------------------
extern "C" void kernel_launch(void* const* d_in, const int* in_sizes, int n_in,
                              void* d_out, int out_size)
{
    const float* x  = (const float*)d_in[0];
    const float* Wq = (const float*)d_in[1];
    const float* Wk = (const float*)d_in[2];
    const float* Wv = (const float*)d_in[3];
    const float* Wo = (const float*)d_in[4];
    const float* W1 = (const float*)d_in[5];
    const float* W2 = (const float*)d_in[6];
    const float* g1 = (const float*)d_in[7];
    const float* b1 = (const float*)d_in[8];
    const float* g2 = (const float*)d_in[9];
    const float* b2 = (const float*)d_in[10];

    float *qkv, *attn, *proj, *x1;
    __nv_bfloat16 *ahi, *alo, *fhi, *flo, *whi, *wlo;
    cudaGetSymbolAddress((void**)&qkv,  g_qkv);
    cudaGetSymbolAddress((void**)&attn, g_attn);
    cudaGetSymbolAddress((void**)&proj, g_proj);
    cudaGetSymbolAddress((void**)&x1,   g_x1);
    cudaGetSymbolAddress((void**)&ahi,  g_ahi);
    cudaGetSymbolAddress((void**)&alo,  g_alo);
    cudaGetSymbolAddress((void**)&fhi,  g_fhi);
    cudaGetSymbolAddress((void**)&flo,  g_flo);
    cudaGetSymbolAddress((void**)&whi,  g_whi);
    cudaGetSymbolAddress((void**)&wlo,  g_wlo);

    cudaFuncSetAttribute(mma_gemm<false, false>,
                         cudaFuncAttributeMaxDynamicSharedMemorySize, SMEM_BYTES);
    cudaFuncSetAttribute(mma_gemm<true, true>,
                         cudaFuncAttributeMaxDynamicSharedMemorySize, SMEM_BYTES);

    dim3 blk(256);
    const int n4_1m = (1024 * 1024) / 4;
    const int n4_4m = (4096 * 1024) / 4;

    // weight + input conversions to (hi, lo) bf16
    convert_hl<<<n4_1m / 256, blk>>>(Wq, whi + OFF_WQ, wlo + OFF_WQ, n4_1m);
    convert_hl<<<n4_1m / 256, blk>>>(Wk, whi + OFF_WK, wlo + OFF_WK, n4_1m);
    convert_hl<<<n4_1m / 256, blk>>>(Wv, whi + OFF_WV, wlo + OFF_WV, n4_1m);
    convert_hl<<<n4_1m / 256, blk>>>(Wo, whi + OFF_WO, wlo + OFF_WO, n4_1m);
    convert_hl<<<n4_4m / 256, blk>>>(W1, whi + OFF_W1, wlo + OFF_W1, n4_4m);
    convert_hl<<<n4_4m / 256, blk>>>(W2, whi + OFF_W2, wlo + OFF_W2, n4_4m);
    convert_hl<<<n4_4m / 256, blk>>>(x, ahi, alo, n4_4m);

    // fused QKV: [4096,1024] x [3072,1024]^T -> [4096,3072]
    mma_gemm<false, false><<<dim3(24, 32), blk, SMEM_BYTES>>>(
        ahi, alo, whi + OFF_WQ, wlo + OFF_WQ, qkv, nullptr, nullptr, BSQ, 3072, 1024);

    // attention on strided QKV
    attn_kernel<<<dim3(32, 32), blk>>>(qkv, qkv + 1024, qkv + 2048, attn, 3072);

    // O projection
    convert_hl<<<n4_4m / 256, blk>>>(attn, ahi, alo, n4_4m);
    mma_gemm<false, false><<<dim3(8, 32), blk, SMEM_BYTES>>>(
        ahi, alo, whi + OFF_WO, wlo + OFF_WO, proj, nullptr, nullptr, BSQ, 1024, 1024);

    // residual + LN1 (writes fp32 x1 + hi/lo for FF1)
    add_ln_kernel<<<BSQ, blk>>>(x, proj, g1, b1, x1, ahi, alo);

    // FF1 + GELU -> bf16 hi/lo directly
    mma_gemm<true, true><<<dim3(32, 32), blk, SMEM_BYTES>>>(
        ahi, alo, whi + OFF_W1, wlo + OFF_W1, nullptr, fhi, flo, BSQ, D_FF, 1024);

    // FF2 (K=4096)
    mma_gemm<false, false><<<dim3(8, 32), blk, SMEM_BYTES>>>(
        fhi, flo, whi + OFF_W2, wlo + OFF_W2, proj, nullptr, nullptr, BSQ, 1024, D_FF);

    // residual + LN2 -> output
    add_ln_kernel<<<BSQ, blk>>>(x1, proj, g2, b2, (float*)d_out, nullptr, nullptr);
}

// round 5
// speedup vs baseline: 2.7806x; 1.4931x over previous
#include <cuda_runtime.h>
#include <cuda_bf16.h>
#include <math.h>
#include <stdint.h>

#define D_MODEL 1024
#define BSQ 4096              // B*S = 2*2048
#define D_FF  4096

// ---------------- scratch (device globals; no allocation allowed) ----------------
__device__ float g_proj[(size_t)BSQ * D_MODEL];
__device__ float g_x1  [(size_t)BSQ * D_MODEL];
__device__ __nv_bfloat16 g_qkvh[(size_t)BSQ * 3072];
__device__ __nv_bfloat16 g_qkvl[(size_t)BSQ * 3072];
__device__ __nv_bfloat16 g_ahi[(size_t)BSQ * D_MODEL];
__device__ __nv_bfloat16 g_alo[(size_t)BSQ * D_MODEL];
__device__ __nv_bfloat16 g_fhi[(size_t)BSQ * D_FF];
__device__ __nv_bfloat16 g_flo[(size_t)BSQ * D_FF];
#define W_ELEMS 12582912   // 3M (QKV) + 1M (Wo) + 4M (W1) + 4M (W2)
__device__ __nv_bfloat16 g_whi[W_ELEMS];
__device__ __nv_bfloat16 g_wlo[W_ELEMS];
#define OFF_WQ 0
#define OFF_WK 1048576
#define OFF_WV 2097152
#define OFF_WO 3145728
#define OFF_W1 4194304
#define OFF_W2 8388608

// ---------------- helpers --------------------------------------------------------
__device__ __forceinline__ uint32_t smem_to_u32(const void* p) {
    uint32_t a;
    asm("{ .reg .u64 t; cvta.to.shared.u64 t, %1; cvt.u32.u64 %0, t; }" : "=r"(a) : "l"(p));
    return a;
}
#define SWZ(off) ((off) ^ (((off) >> 3) & 0x70))

__device__ __forceinline__ void cp_async16(uint32_t dst, const void* src) {
    asm volatile("cp.async.cg.shared.global [%0], [%1], 16;" :: "r"(dst), "l"(src) : "memory");
}
__device__ __forceinline__ void cp_commit() {
    asm volatile("cp.async.commit_group;" ::: "memory");
}
template<int N>
__device__ __forceinline__ void cp_wait() {
    asm volatile("cp.async.wait_group %0;" :: "n"(N) : "memory");
}
__device__ __forceinline__ void ldsm4(uint32_t* r, uint32_t addr) {
    asm volatile("ldmatrix.sync.aligned.m8n8.x4.shared.b16 {%0,%1,%2,%3}, [%4];"
                 : "=r"(r[0]), "=r"(r[1]), "=r"(r[2]), "=r"(r[3]) : "r"(addr));
}
__device__ __forceinline__ void ldsm4t(uint32_t* r, uint32_t addr) {
    asm volatile("ldmatrix.sync.aligned.m8n8.x4.trans.shared.b16 {%0,%1,%2,%3}, [%4];"
                 : "=r"(r[0]), "=r"(r[1]), "=r"(r[2]), "=r"(r[3]) : "r"(addr));
}
__device__ __forceinline__ void mma16816(float* d, const uint32_t* a, const uint32_t* b) {
    asm volatile("mma.sync.aligned.m16n8k16.row.col.f32.bf16.bf16.f32 "
                 "{%0,%1,%2,%3}, {%4,%5,%6,%7}, {%8,%9}, {%0,%1,%2,%3};"
                 : "+f"(d[0]), "+f"(d[1]), "+f"(d[2]), "+f"(d[3])
                 : "r"(a[0]), "r"(a[1]), "r"(a[2]), "r"(a[3]), "r"(b[0]), "r"(b[1]));
}
__device__ __forceinline__ float gelu_exact(float x) {
    return 0.5f * x * (1.0f + erff(x * 0.70710678118654752f));
}
__device__ __forceinline__ uint32_t pack_bf16x2(float x, float y) {
    __nv_bfloat162 t = __floats2bfloat162_rn(x, y);
    return *(uint32_t*)&t;
}

// ---------------- fp32 -> (hi, lo) bf16 split conversion -------------------------
__global__ __launch_bounds__(256)
void convert_hl(const float* __restrict__ src, __nv_bfloat16* __restrict__ hi,
                __nv_bfloat16* __restrict__ lo, int n4)
{
    int i = blockIdx.x * blockDim.x + threadIdx.x;
    if (i >= n4) return;
    float4 v = ((const float4*)src)[i];
    __nv_bfloat16 h0 = __float2bfloat16(v.x), h1 = __float2bfloat16(v.y);
    __nv_bfloat16 h2 = __float2bfloat16(v.z), h3 = __float2bfloat16(v.w);
    __nv_bfloat16 l0 = __float2bfloat16(v.x - __bfloat162float(h0));
    __nv_bfloat16 l1 = __float2bfloat16(v.y - __bfloat162float(h1));
    __nv_bfloat16 l2 = __float2bfloat16(v.z - __bfloat162float(h2));
    __nv_bfloat16 l3 = __float2bfloat16(v.w - __bfloat162float(h3));
    ((__nv_bfloat162*)hi)[2 * i + 0] = __nv_bfloat162(h0, h1);
    ((__nv_bfloat162*)hi)[2 * i + 1] = __nv_bfloat162(h2, h3);
    ((__nv_bfloat162*)lo)[2 * i + 0] = __nv_bfloat162(l0, l1);
    ((__nv_bfloat162*)lo)[2 * i + 1] = __nv_bfloat162(l2, l3);
}

// ---------------- mma.sync GEMM: C[M,N] = A[M,K]*B[N,K]^T (bf16x3 split) ---------
#define STAGE_BYTES 65536
#define SMEM_BYTES  (2 * STAGE_BYTES)

template<bool GELU, bool BF16OUT>
__global__ __launch_bounds__(256)
void mma_gemm(const __nv_bfloat16* __restrict__ Ah, const __nv_bfloat16* __restrict__ Al,
              const __nv_bfloat16* __restrict__ Bh, const __nv_bfloat16* __restrict__ Bl,
              float* __restrict__ C, __nv_bfloat16* __restrict__ Ch,
              __nv_bfloat16* __restrict__ Cl, int M, int N, int K)
{
    extern __shared__ __align__(1024) char smem[];
    const uint32_t sb = smem_to_u32(smem);
    const int tid  = threadIdx.x;
    const int wid  = tid >> 5;
    const int lane = tid & 31;
    const int m0 = blockIdx.y * 128;
    const int n0 = blockIdx.x * 128;
    const int mw = (wid >> 2) * 64;
    const int nw = (wid & 3) * 32;

    float acc[4][4][4];
#pragma unroll
    for (int i = 0; i < 4; i++)
#pragma unroll
        for (int j = 0; j < 4; j++)
#pragma unroll
            for (int e = 0; e < 4; e++) acc[i][j][e] = 0.f;

    const int rsub = tid >> 3;
    const int g    = tid & 7;

    auto load_stage = [&](int t) {
        const int k0 = t << 6;
        const uint32_t stage = sb + (t & 1) * STAGE_BYTES;
#pragma unroll
        for (int i = 0; i < 16; i++) {
            const int mat = i >> 2;
            const int r = (i & 3) * 32 + rsub;
            const __nv_bfloat16* src = (mat == 0) ? Ah : (mat == 1) ? Al
                                      : (mat == 2) ? Bh : Bl;
            const int row0 = (mat < 2) ? m0 : n0;
            cp_async16(stage + mat * 16384 + SWZ(r * 128 + g * 16),
                       &src[(size_t)(row0 + r) * K + k0 + g * 8]);
        }
        cp_commit();
    };

    const int nT = K >> 6;
    load_stage(0);

    for (int t = 0; t < nT; t++) {
        if (t + 1 < nT) { load_stage(t + 1); cp_wait<1>(); }
        else            { cp_wait<0>(); }
        __syncthreads();

        const uint32_t stage = sb + (t & 1) * STAGE_BYTES;
#pragma unroll
        for (int kk = 0; kk < 4; kk++) {
            const int kbyte = kk * 32;
            uint32_t ah[4][4], al[4][4], bh[2][4], bl[2][4];
#pragma unroll
            for (int mt = 0; mt < 4; mt++) {
                const int off = (mw + mt * 16 + (lane & 15)) * 128 + kbyte + (lane >> 4) * 16;
                ldsm4(ah[mt], stage + 0     + SWZ(off));
                ldsm4(al[mt], stage + 16384 + SWZ(off));
            }
#pragma unroll
            for (int p = 0; p < 2; p++) {
                const int off = (nw + p * 16 + (lane >> 4) * 8 + (lane & 7)) * 128
                              + kbyte + ((lane >> 3) & 1) * 16;
                ldsm4(bh[p], stage + 32768 + SWZ(off));
                ldsm4(bl[p], stage + 49152 + SWZ(off));
            }
#pragma unroll
            for (int mt = 0; mt < 4; mt++)
#pragma unroll
                for (int nt = 0; nt < 4; nt++) {
                    const uint32_t* bhf = &bh[nt >> 1][(nt & 1) * 2];
                    const uint32_t* blf = &bl[nt >> 1][(nt & 1) * 2];
                    mma16816(acc[mt][nt], ah[mt], bhf);
                    mma16816(acc[mt][nt], ah[mt], blf);
                    mma16816(acc[mt][nt], al[mt], bhf);
                }
        }
        __syncthreads();
    }

    const int er0 = m0 + mw + (lane >> 2);
    const int ec  = n0 + nw + 2 * (lane & 3);
#pragma unroll
    for (int mt = 0; mt < 4; mt++)
#pragma unroll
        for (int nt = 0; nt < 4; nt++) {
#pragma unroll
            for (int half = 0; half < 2; half++) {
                const int row = er0 + mt * 16 + half * 8;
                const int col = ec + nt * 8;
                float v0 = acc[mt][nt][half * 2 + 0];
                float v1 = acc[mt][nt][half * 2 + 1];
                if (GELU) { v0 = gelu_exact(v0); v1 = gelu_exact(v1); }
                if (BF16OUT) {
                    __nv_bfloat16 h0 = __float2bfloat16(v0);
                    __nv_bfloat16 h1 = __float2bfloat16(v1);
                    __nv_bfloat16 l0 = __float2bfloat16(v0 - __bfloat162float(h0));
                    __nv_bfloat16 l1 = __float2bfloat16(v1 - __bfloat162float(h1));
                    *(__nv_bfloat162*)&Ch[(size_t)row * N + col] = __nv_bfloat162(h0, h1);
                    *(__nv_bfloat162*)&Cl[(size_t)row * N + col] = __nv_bfloat162(l0, l1);
                } else {
                    *(float2*)&C[(size_t)row * N + col] = make_float2(v0, v1);
                }
            }
        }
}

// ---------------- tensor-core flash attention (split-bf16, FA2 layout) -----------
// Block: 128 q-rows of one (b,h). 8 warps, warp w owns q rows 16w..16w+15 and the
// FULL kv width of each 128-wide KV tile. Q/K/V read from strided hi/lo QKV arrays.
#define AT_Q_BYTES  16384
#define AT_STAGE    65536
#define AT_SMEM     (2 * AT_Q_BYTES + 2 * AT_STAGE)   // 163840

__global__ __launch_bounds__(256)
void attn_tc(const __nv_bfloat16* __restrict__ qkvh, const __nv_bfloat16* __restrict__ qkvl,
             __nv_bfloat16* __restrict__ Oh, __nv_bfloat16* __restrict__ Ol)
{
    extern __shared__ __align__(1024) char smem[];
    const uint32_t sb = smem_to_u32(smem);
    const uint32_t sbQ = sb;                 // Qh @0, Ql @16384
    const uint32_t sbS = sb + 2 * AT_Q_BYTES;

    const int tid  = threadIdx.x;
    const int wid  = tid >> 5;
    const int lane = tid & 31;
    const int bh = blockIdx.y;
    const int b  = bh >> 4;
    const int h  = bh & 15;
    const int q0 = blockIdx.x * 128;
    const size_t rowbase = (size_t)b * 2048;
    const int coff = h * 64;

    // ---- async load Q (hi+lo), group A
    {
#pragma unroll
        for (int i = 0; i < 8; i++) {
            const int idx = i * 256 + tid;          // 0..2047
            const int arr = idx >> 10;              // 0=hi, 1=lo
            const int rem = idx & 1023;
            const int row = rem >> 3;
            const int g   = rem & 7;
            const __nv_bfloat16* src = arr ? qkvl : qkvh;
            cp_async16(sbQ + arr * 16384 + SWZ(row * 128 + g * 16),
                       &src[(rowbase + q0 + row) * 3072 + coff + g * 8]);
        }
        cp_commit();
    }

    const int rsub = tid >> 3;
    const int g    = tid & 7;
    auto load_stage = [&](int t) {
        const int kv0 = t << 7;
        const uint32_t stage = sbS + (t & 1) * AT_STAGE;
#pragma unroll
        for (int i = 0; i < 16; i++) {
            const int mat = i >> 2;                 // 0 Kh, 1 Kl, 2 Vh, 3 Vl
            const int r = (i & 3) * 32 + rsub;
            const __nv_bfloat16* src = (mat & 1) ? qkvl : qkvh;
            const int doff = (mat < 2) ? 1024 : 2048;
            cp_async16(stage + mat * 16384 + SWZ(r * 128 + g * 16),
                       &src[(rowbase + kv0 + r) * 3072 + doff + coff + g * 8]);
        }
        cp_commit();
    };

    load_stage(0);

    uint32_t qh[4][4], ql[4][4];
    float oacc[8][4];
    float m_r[2] = {-1e30f, -1e30f}, l_r[2] = {0.f, 0.f};
#pragma unroll
    for (int i = 0; i < 8; i++)
#pragma unroll
        for (int e = 0; e < 4; e++) oacc[i][e] = 0.f;

    for (int t = 0; t < 16; t++) {
        if (t + 1 < 16) { load_stage(t + 1); cp_wait<1>(); }
        else            { cp_wait<0>(); }
        __syncthreads();

        if (t == 0) {
            // Q fragments (once)
#pragma unroll
            for (int kk = 0; kk < 4; kk++) {
                const int off = (wid * 16 + (lane & 15)) * 128 + kk * 32 + (lane >> 4) * 16;
                ldsm4(qh[kk], sbQ + SWZ(off));
                ldsm4(ql[kk], sbQ + 16384 + SWZ(off));
            }
        }

        const uint32_t stage = sbS + (t & 1) * AT_STAGE;

        // ---- S = Q K^T : 16 n8-tiles across 128 kv cols
        float sacc[16][4];
#pragma unroll
        for (int nt = 0; nt < 16; nt++)
#pragma unroll
            for (int e = 0; e < 4; e++) sacc[nt][e] = 0.f;

#pragma unroll
        for (int kk = 0; kk < 4; kk++) {
            const int kbyte = kk * 32;
#pragma unroll
            for (int p = 0; p < 8; p++) {
                uint32_t kh4[4], kl4[4];
                const int off = (p * 16 + (lane >> 4) * 8 + (lane & 7)) * 128
                              + kbyte + ((lane >> 3) & 1) * 16;
                ldsm4(kh4, stage + 0     + SWZ(off));
                ldsm4(kl4, stage + 16384 + SWZ(off));
                mma16816(sacc[2 * p],     qh[kk], kh4);
                mma16816(sacc[2 * p],     qh[kk], kl4);
                mma16816(sacc[2 * p],     ql[kk], kh4);
                mma16816(sacc[2 * p + 1], qh[kk], kh4 + 2);
                mma16816(sacc[2 * p + 1], qh[kk], kl4 + 2);
                mma16816(sacc[2 * p + 1], ql[kk], kh4 + 2);
            }
        }

        // ---- online softmax (scale 0.125 folded into exp)
#pragma unroll
        for (int hf = 0; hf < 2; hf++) {
            float mx = -1e30f;
#pragma unroll
            for (int nt = 0; nt < 16; nt++)
                mx = fmaxf(mx, fmaxf(sacc[nt][2 * hf], sacc[nt][2 * hf + 1]));
            mx = fmaxf(mx, __shfl_xor_sync(0xffffffffu, mx, 1));
            mx = fmaxf(mx, __shfl_xor_sync(0xffffffffu, mx, 2));
            const float mnew = fmaxf(m_r[hf], mx);
            const float corr = __expf((m_r[hf] - mnew) * 0.125f);
            m_r[hf] = mnew;
            float rs = 0.f;
#pragma unroll
            for (int nt = 0; nt < 16; nt++) {
                float p0 = __expf((sacc[nt][2 * hf]     - mnew) * 0.125f);
                float p1 = __expf((sacc[nt][2 * hf + 1] - mnew) * 0.125f);
                sacc[nt][2 * hf] = p0; sacc[nt][2 * hf + 1] = p1;
                rs += p0 + p1;
            }
            rs += __shfl_xor_sync(0xffffffffu, rs, 1);
            rs += __shfl_xor_sync(0xffffffffu, rs, 2);
            l_r[hf] = l_r[hf] * corr + rs;
#pragma unroll
            for (int dn = 0; dn < 8; dn++) {
                oacc[dn][2 * hf]     *= corr;
                oacc[dn][2 * hf + 1] *= corr;
            }
        }

        // ---- O += P V  (P from sacc, split hi/lo in registers)
#pragma unroll
        for (int j = 0; j < 8; j++) {
            uint32_t pah[4], pal[4];
#pragma unroll
            for (int q = 0; q < 4; q++) {
                const float x = sacc[2 * j + (q >> 1)][(q & 1) * 2 + 0];
                const float y = sacc[2 * j + (q >> 1)][(q & 1) * 2 + 1];
                // note: q=0 -> (ntile 2j, rows half0) = a0 ; q=1 -> a1 ; q=2 -> a2 ; q=3 -> a3
                const float xh = __bfloat162float(__float2bfloat16(x));
                const float yh = __bfloat162float(__float2bfloat16(y));
                pah[q] = pack_bf16x2(xh, yh);
                pal[q] = pack_bf16x2(x - xh, y - yh);
            }
            // reorder: built order above is a0=(2j,h0) a1=(2j,h1) a2=(2j+1,h0) a3=(2j+1,h1)
            // required: a0=(2j,h0) a1=(2j,h1) a2=(2j+1,h0) a3=(2j+1,h1) -- matches.
#pragma unroll
            for (int dn16 = 0; dn16 < 4; dn16++) {
                uint32_t vh4[4], vl4[4];
                const int off = (j * 16 + (lane & 7) + ((lane >> 3) & 1) * 8) * 128
                              + dn16 * 32 + (lane >> 4) * 16;
                ldsm4t(vh4, stage + 32768 + SWZ(off));
                ldsm4t(vl4, stage + 49152 + SWZ(off));
                mma16816(oacc[2 * dn16],     pah, vh4);
                mma16816(oacc[2 * dn16],     pah, vl4);
                mma16816(oacc[2 * dn16],     pal, vh4);
                mma16816(oacc[2 * dn16 + 1], pah, vh4 + 2);
                mma16816(oacc[2 * dn16 + 1], pah, vl4 + 2);
                mma16816(oacc[2 * dn16 + 1], pal, vh4 + 2);
            }
        }
        __syncthreads();
    }

    // ---- epilogue: normalize, split hi/lo, store to O layout [BSQ, 1024]
#pragma unroll
    for (int hf = 0; hf < 2; hf++) {
        const float inv = 1.0f / l_r[hf];
        const int row = (int)rowbase + q0 + wid * 16 + (lane >> 2) + hf * 8;
#pragma unroll
        for (int dn = 0; dn < 8; dn++) {
            const int col = coff + dn * 8 + 2 * (lane & 3);
            float v0 = oacc[dn][2 * hf]     * inv;
            float v1 = oacc[dn][2 * hf + 1] * inv;
            __nv_bfloat16 h0 = __float2bfloat16(v0);
            __nv_bfloat16 h1 = __float2bfloat16(v1);
            __nv_bfloat16 l0 = __float2bfloat16(v0 - __bfloat162float(h0));
            __nv_bfloat16 l1 = __float2bfloat16(v1 - __bfloat162float(h1));
            *(__nv_bfloat162*)&Oh[(size_t)row * D_MODEL + col] = __nv_bfloat162(h0, h1);
            *(__nv_bfloat162*)&Ol[(size_t)row * D_MODEL + col] = __nv_bfloat162(l0, l1);
        }
    }
}

// ---------------- fused residual add + LayerNorm (+ optional hi/lo split out) ----
__global__ __launch_bounds__(256)
void add_ln_kernel(const float* __restrict__ X, const float* __restrict__ Y,
                   const float* __restrict__ G, const float* __restrict__ Bv,
                   float* __restrict__ Out, __nv_bfloat16* __restrict__ Hn,
                   __nv_bfloat16* __restrict__ Ln)
{
    const int row = blockIdx.x;
    const int t = threadIdx.x;
    const size_t base = (size_t)row * D_MODEL + t * 4;

    float4 a = *(const float4*)&X[base];
    float4 c = *(const float4*)&Y[base];
    float v0 = a.x + c.x, v1 = a.y + c.y, v2 = a.z + c.z, v3 = a.w + c.w;

    float s  = v0 + v1 + v2 + v3;
    float sq = v0 * v0 + v1 * v1 + v2 * v2 + v3 * v3;
#pragma unroll
    for (int off = 16; off; off >>= 1) {
        s  += __shfl_xor_sync(0xffffffffu, s,  off);
        sq += __shfl_xor_sync(0xffffffffu, sq, off);
    }

    __shared__ float sh_s[8], sh_q[8];
    __shared__ float sh_stats[2];
    const int w = t >> 5, lane = t & 31;
    if (lane == 0) { sh_s[w] = s; sh_q[w] = sq; }
    __syncthreads();
    if (t < 32) {
        float ts = (lane < 8) ? sh_s[lane] : 0.f;
        float tq = (lane < 8) ? sh_q[lane] : 0.f;
#pragma unroll
        for (int off = 4; off; off >>= 1) {
            ts += __shfl_xor_sync(0xffffffffu, ts, off);
            tq += __shfl_xor_sync(0xffffffffu, tq, off);
        }
        if (lane == 0) {
            float mean = ts * (1.0f / D_MODEL);
            float var  = tq * (1.0f / D_MODEL) - mean * mean;
            sh_stats[0] = mean;
            sh_stats[1] = rsqrtf(var + 1e-5f);
        }
    }
    __syncthreads();
    const float mean = sh_stats[0];
    const float rstd = sh_stats[1];

    float4 gg = *(const float4*)&G[t * 4];
    float4 bb = *(const float4*)&Bv[t * 4];
    float4 o;
    o.x = (v0 - mean) * rstd * gg.x + bb.x;
    o.y = (v1 - mean) * rstd * gg.y + bb.y;
    o.z = (v2 - mean) * rstd * gg.z + bb.z;
    o.w = (v3 - mean) * rstd * gg.w + bb.w;
    *(float4*)&Out[base] = o;

    if (Hn) {
        __nv_bfloat16 h0 = __float2bfloat16(o.x), h1 = __float2bfloat16(o.y);
        __nv_bfloat16 h2 = __float2bfloat16(o.z), h3 = __float2bfloat16(o.w);
        __nv_bfloat16 l0 = __float2bfloat16(o.x - __bfloat162float(h0));
        __nv_bfloat16 l1 = __float2bfloat16(o.y - __bfloat162float(h1));
        __nv_bfloat16 l2 = __float2bfloat16(o.z - __bfloat162float(h2));
        __nv_bfloat16 l3 = __float2bfloat16(o.w - __bfloat162float(h3));
        *(__nv_bfloat162*)&Hn[base]     = __nv_bfloat162(h0, h1);
        *(__nv_bfloat162*)&Hn[base + 2] = __nv_bfloat162(h2, h3);
        *(__nv_bfloat162*)&Ln[base]     = __nv_bfloat162(l0, l1);
        *(__nv_bfloat162*)&Ln[base + 2] = __nv_bfloat162(l2, l3);
    }
}

// ---------------- launch --------------------------------------------------------
extern "C" void kernel_launch(void* const* d_in, const int* in_sizes, int n_in,
                              void* d_out, int out_size)
{
    const float* x  = (const float*)d_in[0];
    const float* Wq = (const float*)d_in[1];
    const float* Wk = (const float*)d_in[2];
    const float* Wv = (const float*)d_in[3];
    const float* Wo = (const float*)d_in[4];
    const float* W1 = (const float*)d_in[5];
    const float* W2 = (const float*)d_in[6];
    const float* g1 = (const float*)d_in[7];
    const float* b1 = (const float*)d_in[8];
    const float* g2 = (const float*)d_in[9];
    const float* b2 = (const float*)d_in[10];

    float *proj, *x1;
    __nv_bfloat16 *qkvh, *qkvl, *ahi, *alo, *fhi, *flo, *whi, *wlo;
    cudaGetSymbolAddress((void**)&proj, g_proj);
    cudaGetSymbolAddress((void**)&x1,   g_x1);
    cudaGetSymbolAddress((void**)&qkvh, g_qkvh);
    cudaGetSymbolAddress((void**)&qkvl, g_qkvl);
    cudaGetSymbolAddress((void**)&ahi,  g_ahi);
    cudaGetSymbolAddress((void**)&alo,  g_alo);
    cudaGetSymbolAddress((void**)&fhi,  g_fhi);
    cudaGetSymbolAddress((void**)&flo,  g_flo);
    cudaGetSymbolAddress((void**)&whi,  g_whi);
    cudaGetSymbolAddress((void**)&wlo,  g_wlo);

    cudaFuncSetAttribute(mma_gemm<false, false>,
                         cudaFuncAttributeMaxDynamicSharedMemorySize, SMEM_BYTES);
    cudaFuncSetAttribute(mma_gemm<false, true>,
                         cudaFuncAttributeMaxDynamicSharedMemorySize, SMEM_BYTES);
    cudaFuncSetAttribute(mma_gemm<true, true>,
                         cudaFuncAttributeMaxDynamicSharedMemorySize, SMEM_BYTES);
    cudaFuncSetAttribute(attn_tc,
                         cudaFuncAttributeMaxDynamicSharedMemorySize, AT_SMEM);

    dim3 blk(256);
    const int n4_1m = (1024 * 1024) / 4;
    const int n4_4m = (4096 * 1024) / 4;

    // weight + input conversions to (hi, lo) bf16
    convert_hl<<<n4_1m / 256, blk>>>(Wq, whi + OFF_WQ, wlo + OFF_WQ, n4_1m);
    convert_hl<<<n4_1m / 256, blk>>>(Wk, whi + OFF_WK, wlo + OFF_WK, n4_1m);
    convert_hl<<<n4_1m / 256, blk>>>(Wv, whi + OFF_WV, wlo + OFF_WV, n4_1m);
    convert_hl<<<n4_1m / 256, blk>>>(Wo, whi + OFF_WO, wlo + OFF_WO, n4_1m);
    convert_hl<<<n4_4m / 256, blk>>>(W1, whi + OFF_W1, wlo + OFF_W1, n4_4m);
    convert_hl<<<n4_4m / 256, blk>>>(W2, whi + OFF_W2, wlo + OFF_W2, n4_4m);
    convert_hl<<<n4_4m / 256, blk>>>(x, ahi, alo, n4_4m);

    // fused QKV -> hi/lo bf16 directly
    mma_gemm<false, true><<<dim3(24, 32), blk, SMEM_BYTES>>>(
        ahi, alo, whi + OFF_WQ, wlo + OFF_WQ, nullptr, qkvh, qkvl, BSQ, 3072, 1024);

    // tensor-core flash attention -> hi/lo bf16 (O-proj A operand)
    attn_tc<<<dim3(16, 32), blk, AT_SMEM>>>(qkvh, qkvl, ahi, alo);

    // O projection
    mma_gemm<false, false><<<dim3(8, 32), blk, SMEM_BYTES>>>(
        ahi, alo, whi + OFF_WO, wlo + OFF_WO, proj, nullptr, nullptr, BSQ, 1024, 1024);

    // residual + LN1 (writes fp32 x1 + hi/lo for FF1)
    add_ln_kernel<<<BSQ, blk>>>(x, proj, g1, b1, x1, ahi, alo);

    // FF1 + GELU -> bf16 hi/lo directly
    mma_gemm<true, true><<<dim3(32, 32), blk, SMEM_BYTES>>>(
        ahi, alo, whi + OFF_W1, wlo + OFF_W1, nullptr, fhi, flo, BSQ, D_FF, 1024);

    // FF2 (K=4096)
    mma_gemm<false, false><<<dim3(8, 32), blk, SMEM_BYTES>>>(
        fhi, flo, whi + OFF_W2, wlo + OFF_W2, proj, nullptr, nullptr, BSQ, 1024, D_FF);

    // residual + LN2 -> output
    add_ln_kernel<<<BSQ, blk>>>(x1, proj, g2, b2, (float*)d_out, nullptr, nullptr);
}

// round 6
// speedup vs baseline: 2.8308x; 1.0180x over previous
#include <cuda_runtime.h>
#include <cuda_bf16.h>
#include <math.h>
#include <stdint.h>

#define D_MODEL 1024
#define BSQ 4096              // B*S = 2*2048
#define D_FF  4096

// ---------------- scratch (device globals; no allocation allowed) ----------------
__device__ float g_proj[(size_t)BSQ * D_MODEL];
__device__ float g_x1  [(size_t)BSQ * D_MODEL];
__device__ __nv_bfloat16 g_qkvh[(size_t)BSQ * 3072];
__device__ __nv_bfloat16 g_qkvl[(size_t)BSQ * 3072];
__device__ __nv_bfloat16 g_ahi[(size_t)BSQ * D_MODEL];
__device__ __nv_bfloat16 g_alo[(size_t)BSQ * D_MODEL];
__device__ __nv_bfloat16 g_fhi[(size_t)BSQ * D_FF];
__device__ __nv_bfloat16 g_flo[(size_t)BSQ * D_FF];
#define W_ELEMS 12582912   // 3M (QKV) + 1M (Wo) + 4M (W1) + 4M (W2)
__device__ __nv_bfloat16 g_whi[W_ELEMS];
__device__ __nv_bfloat16 g_wlo[W_ELEMS];
#define OFF_WQ 0
#define OFF_WK 1048576
#define OFF_WV 2097152
#define OFF_WO 3145728
#define OFF_W1 4194304
#define OFF_W2 8388608

// ---------------- helpers --------------------------------------------------------
__device__ __forceinline__ uint32_t smem_to_u32(const void* p) {
    uint32_t a;
    asm("{ .reg .u64 t; cvta.to.shared.u64 t, %1; cvt.u32.u64 %0, t; }" : "=r"(a) : "l"(p));
    return a;
}
#define SWZ(off) ((off) ^ (((off) >> 3) & 0x70))

__device__ __forceinline__ void cp_async16(uint32_t dst, const void* src) {
    asm volatile("cp.async.cg.shared.global [%0], [%1], 16;" :: "r"(dst), "l"(src) : "memory");
}
__device__ __forceinline__ void cp_commit() {
    asm volatile("cp.async.commit_group;" ::: "memory");
}
template<int N>
__device__ __forceinline__ void cp_wait() {
    asm volatile("cp.async.wait_group %0;" :: "n"(N) : "memory");
}
__device__ __forceinline__ void ldsm4(uint32_t* r, uint32_t addr) {
    asm volatile("ldmatrix.sync.aligned.m8n8.x4.shared.b16 {%0,%1,%2,%3}, [%4];"
                 : "=r"(r[0]), "=r"(r[1]), "=r"(r[2]), "=r"(r[3]) : "r"(addr));
}
__device__ __forceinline__ void ldsm4t(uint32_t* r, uint32_t addr) {
    asm volatile("ldmatrix.sync.aligned.m8n8.x4.trans.shared.b16 {%0,%1,%2,%3}, [%4];"
                 : "=r"(r[0]), "=r"(r[1]), "=r"(r[2]), "=r"(r[3]) : "r"(addr));
}
__device__ __forceinline__ void mma16816(float* d, const uint32_t* a, const uint32_t* b) {
    asm volatile("mma.sync.aligned.m16n8k16.row.col.f32.bf16.bf16.f32 "
                 "{%0,%1,%2,%3}, {%4,%5,%6,%7}, {%8,%9}, {%0,%1,%2,%3};"
                 : "+f"(d[0]), "+f"(d[1]), "+f"(d[2]), "+f"(d[3])
                 : "r"(a[0]), "r"(a[1]), "r"(a[2]), "r"(a[3]), "r"(b[0]), "r"(b[1]));
}
__device__ __forceinline__ float gelu_exact(float x) {
    return 0.5f * x * (1.0f + erff(x * 0.70710678118654752f));
}
__device__ __forceinline__ uint32_t pack_bf16x2(float x, float y) {
    __nv_bfloat162 t = __floats2bfloat162_rn(x, y);
    return *(uint32_t*)&t;
}

// ---------------- fused fp32 -> (hi, lo) bf16 split for ALL tensors --------------
// flat float4 index space: [0, 1048576) = Wq/Wk/Wv/Wo (262144 f4 each),
// [1048576, 2097152) = W1, [2097152, 3145728) = W2, [3145728, 4194304) = x
#define CVT_TOTAL_F4 4194304
__global__ __launch_bounds__(256)
void convert_all(const float* __restrict__ Wq, const float* __restrict__ Wk,
                 const float* __restrict__ Wv, const float* __restrict__ Wo,
                 const float* __restrict__ W1, const float* __restrict__ W2,
                 const float* __restrict__ x,
                 __nv_bfloat16* __restrict__ whi, __nv_bfloat16* __restrict__ wlo,
                 __nv_bfloat16* __restrict__ ahi, __nv_bfloat16* __restrict__ alo)
{
    const int i = blockIdx.x * 256 + threadIdx.x;
    const float* src;
    __nv_bfloat16 *hi, *lo;
    int li;
    if (i < 1048576) {
        const int seg = i >> 18;          // 0..3 -> Wq,Wk,Wv,Wo
        li = i & 262143;
        src = (seg == 0) ? Wq : (seg == 1) ? Wk : (seg == 2) ? Wv : Wo;
        hi = whi + (size_t)seg * 1048576;
        lo = wlo + (size_t)seg * 1048576;
    } else if (i < 2097152) {
        li = i - 1048576; src = W1; hi = whi + OFF_W1; lo = wlo + OFF_W1;
    } else if (i < 3145728) {
        li = i - 2097152; src = W2; hi = whi + OFF_W2; lo = wlo + OFF_W2;
    } else {
        li = i - 3145728; src = x; hi = ahi; lo = alo;
    }
    float4 v = ((const float4*)src)[li];
    __nv_bfloat16 h0 = __float2bfloat16(v.x), h1 = __float2bfloat16(v.y);
    __nv_bfloat16 h2 = __float2bfloat16(v.z), h3 = __float2bfloat16(v.w);
    __nv_bfloat16 l0 = __float2bfloat16(v.x - __bfloat162float(h0));
    __nv_bfloat16 l1 = __float2bfloat16(v.y - __bfloat162float(h1));
    __nv_bfloat16 l2 = __float2bfloat16(v.z - __bfloat162float(h2));
    __nv_bfloat16 l3 = __float2bfloat16(v.w - __bfloat162float(h3));
    ((__nv_bfloat162*)hi)[2 * li + 0] = __nv_bfloat162(h0, h1);
    ((__nv_bfloat162*)hi)[2 * li + 1] = __nv_bfloat162(h2, h3);
    ((__nv_bfloat162*)lo)[2 * li + 0] = __nv_bfloat162(l0, l1);
    ((__nv_bfloat162*)lo)[2 * li + 1] = __nv_bfloat162(l2, l3);
}

// ---------------- mma.sync GEMM: C[M,N] = A[M,K]*B[N,K]^T (bf16x3 split) ---------
// 128x128 tile, K_TILE=64, 3-stage cp.async pipeline, 8 warps of 64x32 each.
#define STAGE_BYTES 65536
#define SMEM_BYTES  (3 * STAGE_BYTES)

template<bool GELU, bool BF16OUT>
__global__ __launch_bounds__(256)
void mma_gemm(const __nv_bfloat16* __restrict__ Ah, const __nv_bfloat16* __restrict__ Al,
              const __nv_bfloat16* __restrict__ Bh, const __nv_bfloat16* __restrict__ Bl,
              float* __restrict__ C, __nv_bfloat16* __restrict__ Ch,
              __nv_bfloat16* __restrict__ Cl, int M, int N, int K)
{
    extern __shared__ __align__(1024) char smem[];
    const uint32_t sb = smem_to_u32(smem);
    const int tid  = threadIdx.x;
    const int wid  = tid >> 5;
    const int lane = tid & 31;
    const int m0 = blockIdx.y * 128;
    const int n0 = blockIdx.x * 128;
    const int mw = (wid >> 2) * 64;
    const int nw = (wid & 3) * 32;

    float acc[4][4][4];
#pragma unroll
    for (int i = 0; i < 4; i++)
#pragma unroll
        for (int j = 0; j < 4; j++)
#pragma unroll
            for (int e = 0; e < 4; e++) acc[i][j][e] = 0.f;

    const int rsub = tid >> 3;
    const int g    = tid & 7;

    auto load_stage = [&](int t) {
        const int k0 = t << 6;
        const uint32_t stage = sb + (t % 3) * STAGE_BYTES;
#pragma unroll
        for (int i = 0; i < 16; i++) {
            const int mat = i >> 2;
            const int r = (i & 3) * 32 + rsub;
            const __nv_bfloat16* src = (mat == 0) ? Ah : (mat == 1) ? Al
                                      : (mat == 2) ? Bh : Bl;
            const int row0 = (mat < 2) ? m0 : n0;
            cp_async16(stage + mat * 16384 + SWZ(r * 128 + g * 16),
                       &src[(size_t)(row0 + r) * K + k0 + g * 8]);
        }
        cp_commit();
    };

    const int nT = K >> 6;
    load_stage(0);
    load_stage(1);

    for (int t = 0; t < nT; t++) {
        if (t + 2 < nT)      { load_stage(t + 2); cp_wait<2>(); }
        else if (t + 1 < nT) { cp_wait<1>(); }
        else                 { cp_wait<0>(); }
        __syncthreads();

        const uint32_t stage = sb + (t % 3) * STAGE_BYTES;
#pragma unroll
        for (int kk = 0; kk < 4; kk++) {
            const int kbyte = kk * 32;
            uint32_t ah[4][4], al[4][4], bh[2][4], bl[2][4];
#pragma unroll
            for (int mt = 0; mt < 4; mt++) {
                const int off = (mw + mt * 16 + (lane & 15)) * 128 + kbyte + (lane >> 4) * 16;
                ldsm4(ah[mt], stage + 0     + SWZ(off));
                ldsm4(al[mt], stage + 16384 + SWZ(off));
            }
#pragma unroll
            for (int p = 0; p < 2; p++) {
                const int off = (nw + p * 16 + (lane >> 4) * 8 + (lane & 7)) * 128
                              + kbyte + ((lane >> 3) & 1) * 16;
                ldsm4(bh[p], stage + 32768 + SWZ(off));
                ldsm4(bl[p], stage + 49152 + SWZ(off));
            }
#pragma unroll
            for (int mt = 0; mt < 4; mt++)
#pragma unroll
                for (int nt = 0; nt < 4; nt++) {
                    const uint32_t* bhf = &bh[nt >> 1][(nt & 1) * 2];
                    const uint32_t* blf = &bl[nt >> 1][(nt & 1) * 2];
                    mma16816(acc[mt][nt], ah[mt], bhf);
                    mma16816(acc[mt][nt], ah[mt], blf);
                    mma16816(acc[mt][nt], al[mt], bhf);
                }
        }
        __syncthreads();
    }

    const int er0 = m0 + mw + (lane >> 2);
    const int ec  = n0 + nw + 2 * (lane & 3);
#pragma unroll
    for (int mt = 0; mt < 4; mt++)
#pragma unroll
        for (int nt = 0; nt < 4; nt++) {
#pragma unroll
            for (int half = 0; half < 2; half++) {
                const int row = er0 + mt * 16 + half * 8;
                const int col = ec + nt * 8;
                float v0 = acc[mt][nt][half * 2 + 0];
                float v1 = acc[mt][nt][half * 2 + 1];
                if (GELU) { v0 = gelu_exact(v0); v1 = gelu_exact(v1); }
                if (BF16OUT) {
                    __nv_bfloat16 h0 = __float2bfloat16(v0);
                    __nv_bfloat16 h1 = __float2bfloat16(v1);
                    __nv_bfloat16 l0 = __float2bfloat16(v0 - __bfloat162float(h0));
                    __nv_bfloat16 l1 = __float2bfloat16(v1 - __bfloat162float(h1));
                    *(__nv_bfloat162*)&Ch[(size_t)row * N + col] = __nv_bfloat162(h0, h1);
                    *(__nv_bfloat162*)&Cl[(size_t)row * N + col] = __nv_bfloat162(l0, l1);
                } else {
                    *(float2*)&C[(size_t)row * N + col] = make_float2(v0, v1);
                }
            }
        }
}

// ---------------- tensor-core flash attention (split-bf16, FA2 layout) -----------
// Block: 128 q-rows of one (b,h). 8 warps, warp w owns q rows 16w..16w+15 and the
// FULL kv width of each 128-wide KV tile. 3-stage KV pipeline.
#define AT_Q_BYTES  16384
#define AT_STAGE    65536
#define AT_SMEM     (2 * AT_Q_BYTES + 3 * AT_STAGE)   // 229376

__global__ __launch_bounds__(256)
void attn_tc(const __nv_bfloat16* __restrict__ qkvh, const __nv_bfloat16* __restrict__ qkvl,
             __nv_bfloat16* __restrict__ Oh, __nv_bfloat16* __restrict__ Ol)
{
    extern __shared__ __align__(1024) char smem[];
    const uint32_t sb = smem_to_u32(smem);
    const uint32_t sbQ = sb;                 // Qh @0, Ql @16384
    const uint32_t sbS = sb + 2 * AT_Q_BYTES;

    const int tid  = threadIdx.x;
    const int wid  = tid >> 5;
    const int lane = tid & 31;
    const int bh = blockIdx.y;
    const int b  = bh >> 4;
    const int h  = bh & 15;
    const int q0 = blockIdx.x * 128;
    const size_t rowbase = (size_t)b * 2048;
    const int coff = h * 64;

    // ---- async load Q (hi+lo), its own group
    {
#pragma unroll
        for (int i = 0; i < 8; i++) {
            const int idx = i * 256 + tid;          // 0..2047
            const int arr = idx >> 10;              // 0=hi, 1=lo
            const int rem = idx & 1023;
            const int row = rem >> 3;
            const int g   = rem & 7;
            const __nv_bfloat16* src = arr ? qkvl : qkvh;
            cp_async16(sbQ + arr * 16384 + SWZ(row * 128 + g * 16),
                       &src[(rowbase + q0 + row) * 3072 + coff + g * 8]);
        }
        cp_commit();
    }

    const int rsub = tid >> 3;
    const int g    = tid & 7;
    auto load_stage = [&](int t) {
        const int kv0 = t << 7;
        const uint32_t stage = sbS + (t % 3) * AT_STAGE;
#pragma unroll
        for (int i = 0; i < 16; i++) {
            const int mat = i >> 2;                 // 0 Kh, 1 Kl, 2 Vh, 3 Vl
            const int r = (i & 3) * 32 + rsub;
            const __nv_bfloat16* src = (mat & 1) ? qkvl : qkvh;
            const int doff = (mat < 2) ? 1024 : 2048;
            cp_async16(stage + mat * 16384 + SWZ(r * 128 + g * 16),
                       &src[(rowbase + kv0 + r) * 3072 + doff + coff + g * 8]);
        }
        cp_commit();
    };

    load_stage(0);
    load_stage(1);

    uint32_t qh[4][4], ql[4][4];
    float oacc[8][4];
    float m_r[2] = {-1e30f, -1e30f}, l_r[2] = {0.f, 0.f};
#pragma unroll
    for (int i = 0; i < 8; i++)
#pragma unroll
        for (int e = 0; e < 4; e++) oacc[i][e] = 0.f;

    for (int t = 0; t < 16; t++) {
        if (t + 2 < 16)      { load_stage(t + 2); cp_wait<2>(); }
        else if (t + 1 < 16) { cp_wait<1>(); }
        else                 { cp_wait<0>(); }
        __syncthreads();

        if (t == 0) {
            // Q fragments (once; Q group completed before stage 0 by ordering)
#pragma unroll
            for (int kk = 0; kk < 4; kk++) {
                const int off = (wid * 16 + (lane & 15)) * 128 + kk * 32 + (lane >> 4) * 16;
                ldsm4(qh[kk], sbQ + SWZ(off));
                ldsm4(ql[kk], sbQ + 16384 + SWZ(off));
            }
        }

        const uint32_t stage = sbS + (t % 3) * AT_STAGE;

        // ---- S = Q K^T : 16 n8-tiles across 128 kv cols
        float sacc[16][4];
#pragma unroll
        for (int nt = 0; nt < 16; nt++)
#pragma unroll
            for (int e = 0; e < 4; e++) sacc[nt][e] = 0.f;

#pragma unroll
        for (int kk = 0; kk < 4; kk++) {
            const int kbyte = kk * 32;
#pragma unroll
            for (int p = 0; p < 8; p++) {
                uint32_t kh4[4], kl4[4];
                const int off = (p * 16 + (lane >> 4) * 8 + (lane & 7)) * 128
                              + kbyte + ((lane >> 3) & 1) * 16;
                ldsm4(kh4, stage + 0     + SWZ(off));
                ldsm4(kl4, stage + 16384 + SWZ(off));
                mma16816(sacc[2 * p],     qh[kk], kh4);
                mma16816(sacc[2 * p],     qh[kk], kl4);
                mma16816(sacc[2 * p],     ql[kk], kh4);
                mma16816(sacc[2 * p + 1], qh[kk], kh4 + 2);
                mma16816(sacc[2 * p + 1], qh[kk], kl4 + 2);
                mma16816(sacc[2 * p + 1], ql[kk], kh4 + 2);
            }
        }

        // ---- online softmax (scale 0.125 folded into exp)
#pragma unroll
        for (int hf = 0; hf < 2; hf++) {
            float mx = -1e30f;
#pragma unroll
            for (int nt = 0; nt < 16; nt++)
                mx = fmaxf(mx, fmaxf(sacc[nt][2 * hf], sacc[nt][2 * hf + 1]));
            mx = fmaxf(mx, __shfl_xor_sync(0xffffffffu, mx, 1));
            mx = fmaxf(mx, __shfl_xor_sync(0xffffffffu, mx, 2));
            const float mnew = fmaxf(m_r[hf], mx);
            const float corr = __expf((m_r[hf] - mnew) * 0.125f);
            m_r[hf] = mnew;
            float rs = 0.f;
#pragma unroll
            for (int nt = 0; nt < 16; nt++) {
                float p0 = __expf((sacc[nt][2 * hf]     - mnew) * 0.125f);
                float p1 = __expf((sacc[nt][2 * hf + 1] - mnew) * 0.125f);
                sacc[nt][2 * hf] = p0; sacc[nt][2 * hf + 1] = p1;
                rs += p0 + p1;
            }
            rs += __shfl_xor_sync(0xffffffffu, rs, 1);
            rs += __shfl_xor_sync(0xffffffffu, rs, 2);
            l_r[hf] = l_r[hf] * corr + rs;
#pragma unroll
            for (int dn = 0; dn < 8; dn++) {
                oacc[dn][2 * hf]     *= corr;
                oacc[dn][2 * hf + 1] *= corr;
            }
        }

        // ---- O += P V  (P from sacc, split hi/lo in registers)
#pragma unroll
        for (int j = 0; j < 8; j++) {
            uint32_t pah[4], pal[4];
#pragma unroll
            for (int q = 0; q < 4; q++) {
                const float x = sacc[2 * j + (q >> 1)][(q & 1) * 2 + 0];
                const float y = sacc[2 * j + (q >> 1)][(q & 1) * 2 + 1];
                const float xh = __bfloat162float(__float2bfloat16(x));
                const float yh = __bfloat162float(__float2bfloat16(y));
                pah[q] = pack_bf16x2(xh, yh);
                pal[q] = pack_bf16x2(x - xh, y - yh);
            }
#pragma unroll
            for (int dn16 = 0; dn16 < 4; dn16++) {
                uint32_t vh4[4], vl4[4];
                const int off = (j * 16 + (lane & 7) + ((lane >> 3) & 1) * 8) * 128
                              + dn16 * 32 + (lane >> 4) * 16;
                ldsm4t(vh4, stage + 32768 + SWZ(off));
                ldsm4t(vl4, stage + 49152 + SWZ(off));
                mma16816(oacc[2 * dn16],     pah, vh4);
                mma16816(oacc[2 * dn16],     pah, vl4);
                mma16816(oacc[2 * dn16],     pal, vh4);
                mma16816(oacc[2 * dn16 + 1], pah, vh4 + 2);
                mma16816(oacc[2 * dn16 + 1], pah, vl4 + 2);
                mma16816(oacc[2 * dn16 + 1], pal, vh4 + 2);
            }
        }
        __syncthreads();
    }

    // ---- epilogue: normalize, split hi/lo, store to O layout [BSQ, 1024]
#pragma unroll
    for (int hf = 0; hf < 2; hf++) {
        const float inv = 1.0f / l_r[hf];
        const int row = (int)rowbase + q0 + wid * 16 + (lane >> 2) + hf * 8;
#pragma unroll
        for (int dn = 0; dn < 8; dn++) {
            const int col = coff + dn * 8 + 2 * (lane & 3);
            float v0 = oacc[dn][2 * hf]     * inv;
            float v1 = oacc[dn][2 * hf + 1] * inv;
            __nv_bfloat16 h0 = __float2bfloat16(v0);
            __nv_bfloat16 h1 = __float2bfloat16(v1);
            __nv_bfloat16 l0 = __float2bfloat16(v0 - __bfloat162float(h0));
            __nv_bfloat16 l1 = __float2bfloat16(v1 - __bfloat162float(h1));
            *(__nv_bfloat162*)&Oh[(size_t)row * D_MODEL + col] = __nv_bfloat162(h0, h1);
            *(__nv_bfloat162*)&Ol[(size_t)row * D_MODEL + col] = __nv_bfloat162(l0, l1);
        }
    }
}

// ---------------- fused residual add + LayerNorm (+ optional hi/lo split out) ----
__global__ __launch_bounds__(256)
void add_ln_kernel(const float* __restrict__ X, const float* __restrict__ Y,
                   const float* __restrict__ G, const float* __restrict__ Bv,
                   float* __restrict__ Out, __nv_bfloat16* __restrict__ Hn,
                   __nv_bfloat16* __restrict__ Ln)
{
    const int row = blockIdx.x;
    const int t = threadIdx.x;
    const size_t base = (size_t)row * D_MODEL + t * 4;

    float4 a = *(const float4*)&X[base];
    float4 c = *(const float4*)&Y[base];
    float v0 = a.x + c.x, v1 = a.y + c.y, v2 = a.z + c.z, v3 = a.w + c.w;

    float s  = v0 + v1 + v2 + v3;
    float sq = v0 * v0 + v1 * v1 + v2 * v2 + v3 * v3;
#pragma unroll
    for (int off = 16; off; off >>= 1) {
        s  += __shfl_xor_sync(0xffffffffu, s,  off);
        sq += __shfl_xor_sync(0xffffffffu, sq, off);
    }

    __shared__ float sh_s[8], sh_q[8];
    __shared__ float sh_stats[2];
    const int w = t >> 5, lane = t & 31;
    if (lane == 0) { sh_s[w] = s; sh_q[w] = sq; }
    __syncthreads();
    if (t < 32) {
        float ts = (lane < 8) ? sh_s[lane] : 0.f;
        float tq = (lane < 8) ? sh_q[lane] : 0.f;
#pragma unroll
        for (int off = 4; off; off >>= 1) {
            ts += __shfl_xor_sync(0xffffffffu, ts, off);
            tq += __shfl_xor_sync(0xffffffffu, tq, off);
        }
        if (lane == 0) {
            float mean = ts * (1.0f / D_MODEL);
            float var  = tq * (1.0f / D_MODEL) - mean * mean;
            sh_stats[0] = mean;
            sh_stats[1] = rsqrtf(var + 1e-5f);
        }
    }
    __syncthreads();
    const float mean = sh_stats[0];
    const float rstd = sh_stats[1];

    float4 gg = *(const float4*)&G[t * 4];
    float4 bb = *(const float4*)&Bv[t * 4];
    float4 o;
    o.x = (v0 - mean) * rstd * gg.x + bb.x;
    o.y = (v1 - mean) * rstd * gg.y + bb.y;
    o.z = (v2 - mean) * rstd * gg.z + bb.z;
    o.w = (v3 - mean) * rstd * gg.w + bb.w;
    *(float4*)&Out[base] = o;

    if (Hn) {
        __nv_bfloat16 h0 = __float2bfloat16(o.x), h1 = __float2bfloat16(o.y);
        __nv_bfloat16 h2 = __float2bfloat16(o.z), h3 = __float2bfloat16(o.w);
        __nv_bfloat16 l0 = __float2bfloat16(o.x - __bfloat162float(h0));
        __nv_bfloat16 l1 = __float2bfloat16(o.y - __bfloat162float(h1));
        __nv_bfloat16 l2 = __float2bfloat16(o.z - __bfloat162float(h2));
        __nv_bfloat16 l3 = __float2bfloat16(o.w - __bfloat162float(h3));
        *(__nv_bfloat162*)&Hn[base]     = __nv_bfloat162(h0, h1);
        *(__nv_bfloat162*)&Hn[base + 2] = __nv_bfloat162(h2, h3);
        *(__nv_bfloat162*)&Ln[base]     = __nv_bfloat162(l0, l1);
        *(__nv_bfloat162*)&Ln[base + 2] = __nv_bfloat162(l2, l3);
    }
}

// ---------------- launch --------------------------------------------------------
extern "C" void kernel_launch(void* const* d_in, const int* in_sizes, int n_in,
                              void* d_out, int out_size)
{
    const float* x  = (const float*)d_in[0];
    const float* Wq = (const float*)d_in[1];
    const float* Wk = (const float*)d_in[2];
    const float* Wv = (const float*)d_in[3];
    const float* Wo = (const float*)d_in[4];
    const float* W1 = (const float*)d_in[5];
    const float* W2 = (const float*)d_in[6];
    const float* g1 = (const float*)d_in[7];
    const float* b1 = (const float*)d_in[8];
    const float* g2 = (const float*)d_in[9];
    const float* b2 = (const float*)d_in[10];

    float *proj, *x1;
    __nv_bfloat16 *qkvh, *qkvl, *ahi, *alo, *fhi, *flo, *whi, *wlo;
    cudaGetSymbolAddress((void**)&proj, g_proj);
    cudaGetSymbolAddress((void**)&x1,   g_x1);
    cudaGetSymbolAddress((void**)&qkvh, g_qkvh);
    cudaGetSymbolAddress((void**)&qkvl, g_qkvl);
    cudaGetSymbolAddress((void**)&ahi,  g_ahi);
    cudaGetSymbolAddress((void**)&alo,  g_alo);
    cudaGetSymbolAddress((void**)&fhi,  g_fhi);
    cudaGetSymbolAddress((void**)&flo,  g_flo);
    cudaGetSymbolAddress((void**)&whi,  g_whi);
    cudaGetSymbolAddress((void**)&wlo,  g_wlo);

    cudaFuncSetAttribute(mma_gemm<false, false>,
                         cudaFuncAttributeMaxDynamicSharedMemorySize, SMEM_BYTES);
    cudaFuncSetAttribute(mma_gemm<false, true>,
                         cudaFuncAttributeMaxDynamicSharedMemorySize, SMEM_BYTES);
    cudaFuncSetAttribute(mma_gemm<true, true>,
                         cudaFuncAttributeMaxDynamicSharedMemorySize, SMEM_BYTES);
    cudaFuncSetAttribute(attn_tc,
                         cudaFuncAttributeMaxDynamicSharedMemorySize, AT_SMEM);

    dim3 blk(256);

    // fused weight + input conversions to (hi, lo) bf16 — single launch
    convert_all<<<CVT_TOTAL_F4 / 256, blk>>>(Wq, Wk, Wv, Wo, W1, W2, x,
                                             whi, wlo, ahi, alo);

    // fused QKV -> hi/lo bf16 directly
    mma_gemm<false, true><<<dim3(24, 32), blk, SMEM_BYTES>>>(
        ahi, alo, whi + OFF_WQ, wlo + OFF_WQ, nullptr, qkvh, qkvl, BSQ, 3072, 1024);

    // tensor-core flash attention -> hi/lo bf16 (O-proj A operand)
    attn_tc<<<dim3(16, 32), blk, AT_SMEM>>>(qkvh, qkvl, ahi, alo);

    // O projection
    mma_gemm<false, false><<<dim3(8, 32), blk, SMEM_BYTES>>>(
        ahi, alo, whi + OFF_WO, wlo + OFF_WO, proj, nullptr, nullptr, BSQ, 1024, 1024);

    // residual + LN1 (writes fp32 x1 + hi/lo for FF1)
    add_ln_kernel<<<BSQ, blk>>>(x, proj, g1, b1, x1, ahi, alo);

    // FF1 + GELU -> bf16 hi/lo directly
    mma_gemm<true, true><<<dim3(32, 32), blk, SMEM_BYTES>>>(
        ahi, alo, whi + OFF_W1, wlo + OFF_W1, nullptr, fhi, flo, BSQ, D_FF, 1024);

    // FF2 (K=4096)
    mma_gemm<false, false><<<dim3(8, 32), blk, SMEM_BYTES>>>(
        fhi, flo, whi + OFF_W2, wlo + OFF_W2, proj, nullptr, nullptr, BSQ, 1024, D_FF);

    // residual + LN2 -> output
    add_ln_kernel<<<BSQ, blk>>>(x1, proj, g2, b2, (float*)d_out, nullptr, nullptr);
}